// round 3
// baseline (speedup 1.0000x reference)
#include <cuda_runtime.h>
#include <cuda_bf16.h>
#include <math.h>

// Problem constants (fixed by the reference)
#define N_MAX   50000
#define E_MAX   640000
#define FEAT    128
#define EMB     128
#define HID     512
#define BDIM    32

// ---------------- scratch (static device globals: allocation-guard safe) ---
__device__ int   g_deg [N_MAX];
__device__ int   g_ptr [N_MAX + 1];
__device__ int   g_fill[N_MAX];
__device__ int   g_srcs[E_MAX];
__device__ float g_t   [N_MAX * EMB];   // h @ W_rel
__device__ float g_root[N_MAX * EMB];   // h @ W_root + b
__device__ float g_h   [N_MAX * EMB];   // layer output
__device__ float g_m   [BDIM * EMB];    // message embed
__device__ unsigned g_colmax[BDIM];     // encoded-float max per column
__device__ float    g_colsum[BDIM];
__device__ int   g_is64;

// ---------------- helpers --------------------------------------------------
__device__ __forceinline__ unsigned fenc(float f) {
    unsigned u = __float_as_uint(f);
    return (u & 0x80000000u) ? ~u : (u | 0x80000000u);
}
__device__ __forceinline__ float fdec(unsigned u) {
    return (u & 0x80000000u) ? __uint_as_float(u & 0x7FFFFFFFu)
                             : __uint_as_float(~u);
}
__device__ __forceinline__ int edge_at(const void* ei, long long idx) {
    if (g_is64) return (int)((const long long*)ei)[idx];
    return ((const int*)ei)[idx];
}

// ---------------- 0. dtype detect (int64 vs silently-downcast int32) -------
__global__ void detect_kernel(const void* ei, int n) {
    if (blockIdx.x == 0 && threadIdx.x == 0) {
        const long long* p = (const long long*)ei;
        int ok = 1;
        for (int i = 0; i < 256; i++) {
            long long v = p[i];
            if (v < 0 || v >= (long long)n) { ok = 0; break; }
        }
        g_is64 = ok;
    }
}

// ---------------- 1. init --------------------------------------------------
__global__ void init_kernel(int n) {
    int i = blockIdx.x * blockDim.x + threadIdx.x;
    if (i < n) { g_deg[i] = 0; g_fill[i] = 0; }
    if (i < BDIM) { g_colmax[i] = 0u; g_colsum[i] = 0.0f; }
}

// ---------------- 2. degree histogram --------------------------------------
__global__ void hist_kernel(const void* ei, int e) {
    int i = blockIdx.x * blockDim.x + threadIdx.x;
    if (i < e) {
        int d = edge_at(ei, (long long)e + i);
        atomicAdd(&g_deg[d], 1);
    }
}

// ---------------- 3. exclusive scan (single block, shuffle-based) ----------
__global__ void scan_kernel(int n) {
    __shared__ int warp_sums[32];
    __shared__ int tile_carry;
    int tid  = threadIdx.x;
    int lane = tid & 31;
    int wrp  = tid >> 5;
    if (tid == 0) tile_carry = 0;
    __syncthreads();
    for (int base = 0; base < n; base += 1024) {
        int i = base + tid;
        int v = (i < n) ? g_deg[i] : 0;
        int s = v;
        #pragma unroll
        for (int off = 1; off < 32; off <<= 1) {
            int t = __shfl_up_sync(0xFFFFFFFFu, s, off);
            if (lane >= off) s += t;
        }
        if (lane == 31) warp_sums[wrp] = s;
        __syncthreads();
        int carry = tile_carry;
        if (wrp == 0) {
            int ws = warp_sums[lane];
            int ss = ws;
            #pragma unroll
            for (int off = 1; off < 32; off <<= 1) {
                int t = __shfl_up_sync(0xFFFFFFFFu, ss, off);
                if (lane >= off) ss += t;
            }
            warp_sums[lane] = ss - ws;     // exclusive warp offsets
            if (lane == 31) tile_carry = carry + ss;
        }
        __syncthreads();
        if (i < n) g_ptr[i] = carry + warp_sums[wrp] + s - v;   // exclusive
    }
    if (tid == 0) g_ptr[n] = tile_carry;
}

// ---------------- 4. CSR fill ------------------------------------------------
__global__ void fill_kernel(const void* ei, int e) {
    int i = blockIdx.x * blockDim.x + threadIdx.x;
    if (i < e) {
        int d = edge_at(ei, (long long)e + i);
        int s = edge_at(ei, (long long)i);
        int pos = g_ptr[d] + atomicAdd(&g_fill[d], 1);
        g_srcs[pos] = s;
    }
}

// ---------------- 5. layer GEMM: t = A@W_rel ; root = A@W_root + b ----------
// Block 256 threads, 64-row tile. Thread: 8 rows x 4 cols, rows paired into
// fma.rn.f32x2 (FFMA2) accumulators. A==nullptr means read from g_h.
__global__ __launch_bounds__(256) void rgcn_gemm_kernel(
        const float* __restrict__ A,
        const float* __restrict__ Wrel,
        const float* __restrict__ Wroot,
        const float* __restrict__ bias,
        int n)
{
    const float* Ap = A ? A : g_h;
    const float* W  = (blockIdx.y == 0) ? Wrel : Wroot;
    float*       O  = (blockIdx.y == 0) ? g_t  : g_root;

    __shared__ float sAT[32 * 64];     // [k][row]  (transposed A tile)
    __shared__ float sB [32 * 128];    // [k][col]

    int tid  = threadIdx.x;
    int cid  = tid & 31;               // column quad (cols cid*4..+3)
    int wid  = tid >> 5;               // row group  (rows wid*8..+7)
    int row0 = blockIdx.x * 64;

    unsigned long long acc[4][4];      // [rowpair][col] ; pair = rows (2p,2p+1)
    #pragma unroll
    for (int p = 0; p < 4; p++)
        #pragma unroll
        for (int c = 0; c < 4; c++) acc[p][c] = 0ULL;

    for (int k0 = 0; k0 < FEAT; k0 += 32) {
        #pragma unroll
        for (int i = 0; i < 2; i++) {
            int li = tid + i * 256;            // 0..511
            int r = li >> 3, q = li & 7;       // r 0..63, q 0..7
            int gr = row0 + r;
            float4 v = make_float4(0.f, 0.f, 0.f, 0.f);
            if (gr < n) v = *(const float4*)&Ap[gr * FEAT + k0 + q * 4];
            sAT[(q * 4 + 0) * 64 + r] = v.x;
            sAT[(q * 4 + 1) * 64 + r] = v.y;
            sAT[(q * 4 + 2) * 64 + r] = v.z;
            sAT[(q * 4 + 3) * 64 + r] = v.w;
        }
        #pragma unroll
        for (int i = 0; i < 4; i++) {
            int li = tid + i * 256;            // 0..1023
            int r = li >> 5, q = li & 31;
            *(float4*)&sB[r * 128 + q * 4] =
                *(const float4*)&W[(k0 + r) * EMB + q * 4];
        }
        __syncthreads();

        #pragma unroll
        for (int kk = 0; kk < 32; kk++) {
            unsigned long long ap[4];
            #pragma unroll
            for (int p = 0; p < 4; p++)
                ap[p] = *(const unsigned long long*)
                            &sAT[kk * 64 + wid * 8 + p * 2];
            float4 bv = *(const float4*)&sB[kk * 128 + cid * 4];
            unsigned long long bd[4];
            unsigned bu;
            bu = __float_as_uint(bv.x);
            asm("mov.b64 %0, {%1, %1};" : "=l"(bd[0]) : "r"(bu));
            bu = __float_as_uint(bv.y);
            asm("mov.b64 %0, {%1, %1};" : "=l"(bd[1]) : "r"(bu));
            bu = __float_as_uint(bv.z);
            asm("mov.b64 %0, {%1, %1};" : "=l"(bd[2]) : "r"(bu));
            bu = __float_as_uint(bv.w);
            asm("mov.b64 %0, {%1, %1};" : "=l"(bd[3]) : "r"(bu));
            #pragma unroll
            for (int p = 0; p < 4; p++)
                #pragma unroll
                for (int c = 0; c < 4; c++)
                    asm("fma.rn.f32x2 %0, %1, %2, %0;"
                        : "+l"(acc[p][c]) : "l"(ap[p]), "l"(bd[c]));
        }
        __syncthreads();
    }

    float4 bb = make_float4(0.f, 0.f, 0.f, 0.f);
    if (blockIdx.y == 1) bb = *(const float4*)&bias[cid * 4];

    #pragma unroll
    for (int p = 0; p < 4; p++) {
        float lo[4], hi[4];
        #pragma unroll
        for (int c = 0; c < 4; c++) {
            unsigned ulo, uhi;
            asm("mov.b64 {%0, %1}, %2;" : "=r"(ulo), "=r"(uhi) : "l"(acc[p][c]));
            lo[c] = __uint_as_float(ulo);
            hi[c] = __uint_as_float(uhi);
        }
        int r0 = row0 + wid * 8 + p * 2;
        if (r0 < n)
            *(float4*)&O[r0 * EMB + cid * 4] =
                make_float4(lo[0] + bb.x, lo[1] + bb.y, lo[2] + bb.z, lo[3] + bb.w);
        if (r0 + 1 < n)
            *(float4*)&O[(r0 + 1) * EMB + cid * 4] =
                make_float4(hi[0] + bb.x, hi[1] + bb.y, hi[2] + bb.z, hi[3] + bb.w);
    }
}

// ---------------- 6. aggregate (warp per node, CSR gather, unroll 4) --------
__global__ __launch_bounds__(256) void agg_kernel(int n) {
    int idx  = blockIdx.x * blockDim.x + threadIdx.x;
    int g    = idx >> 5;
    int lane = idx & 31;
    if (g >= n) return;
    int beg = __ldg(&g_ptr[g]), end = __ldg(&g_ptr[g + 1]);
    const float4* t4 = (const float4*)g_t;
    float4 a0 = make_float4(0.f, 0.f, 0.f, 0.f);
    float4 a1 = make_float4(0.f, 0.f, 0.f, 0.f);
    float4 a2 = make_float4(0.f, 0.f, 0.f, 0.f);
    float4 a3 = make_float4(0.f, 0.f, 0.f, 0.f);
    int e = beg;
    for (; e + 4 <= end; e += 4) {
        int s0 = __ldg(&g_srcs[e]);
        int s1 = __ldg(&g_srcs[e + 1]);
        int s2 = __ldg(&g_srcs[e + 2]);
        int s3 = __ldg(&g_srcs[e + 3]);
        float4 v0 = t4[s0 * 32 + lane];
        float4 v1 = t4[s1 * 32 + lane];
        float4 v2 = t4[s2 * 32 + lane];
        float4 v3 = t4[s3 * 32 + lane];
        a0.x += v0.x; a0.y += v0.y; a0.z += v0.z; a0.w += v0.w;
        a1.x += v1.x; a1.y += v1.y; a1.z += v1.z; a1.w += v1.w;
        a2.x += v2.x; a2.y += v2.y; a2.z += v2.z; a2.w += v2.w;
        a3.x += v3.x; a3.y += v3.y; a3.z += v3.z; a3.w += v3.w;
    }
    for (; e < end; e++) {
        int s = __ldg(&g_srcs[e]);
        float4 v = t4[s * 32 + lane];
        a0.x += v.x; a0.y += v.y; a0.z += v.z; a0.w += v.w;
    }
    a0.x += a2.x; a0.y += a2.y; a0.z += a2.z; a0.w += a2.w;
    a1.x += a3.x; a1.y += a3.y; a1.z += a3.z; a1.w += a3.w;
    float inv = 1.0f / fmaxf((float)(end - beg), 1.0f);
    float4 r = ((const float4*)g_root)[g * 32 + lane];
    float4 h;
    h.x = fmaxf((a0.x + a1.x) * inv + r.x, 0.0f);
    h.y = fmaxf((a0.y + a1.y) * inv + r.y, 0.0f);
    h.z = fmaxf((a0.z + a1.z) * inv + r.z, 0.0f);
    h.w = fmaxf((a0.w + a1.w) * inv + r.w, 0.0f);
    ((float4*)g_h)[g * 32 + lane] = h;
}

// ---------------- 7. projection m = lh @ Wp + bp  [32,128] ------------------
__global__ void proj_kernel(const float* __restrict__ lh,
                            const float* __restrict__ Wp,
                            const float* __restrict__ bp) {
    __shared__ float sl[HID];
    int b = blockIdx.x;                     // 0..31
    int c = threadIdx.x;                    // 0..127
    for (int k = c; k < HID; k += 128) sl[k] = lh[b * HID + k];
    __syncthreads();
    float acc = bp[c];
    #pragma unroll 8
    for (int k = 0; k < HID; k++) acc += sl[k] * Wp[k * EMB + c];
    g_m[b * EMB + c] = acc;
}

// ---------------- 8. scores = h2 @ m^T  [n,32]  + fused column max ----------
__global__ __launch_bounds__(256) void scores_kernel(float* __restrict__ scores,
                                                     int n) {
    __shared__ float sM[128 * 32];          // transposed m: sM[k*32 + b]
    __shared__ float sA[64 * 68];           // 64 rows x 64-k chunk, pad 4
    __shared__ float sMax[8][32];           // per-warp column maxima
    int tid = threadIdx.x;
    for (int i = tid; i < BDIM * EMB; i += 256) {
        int b = i >> 7, k = i & 127;
        sM[k * 32 + b] = g_m[i];
    }
    int row0 = blockIdx.x * 64;
    int cid = tid & 7;                      // col quad (b = cid*4..+3)
    int rid = tid >> 3;                     // 0..31 ; rows rid, rid+32
    float acc0[4] = {0.f, 0.f, 0.f, 0.f};
    float acc1[4] = {0.f, 0.f, 0.f, 0.f};
    for (int k0 = 0; k0 < 128; k0 += 64) {
        __syncthreads();
        for (int i = tid; i < 64 * 16; i += 256) {     // 16 float4 per row
            int r = i >> 4, q = i & 15;
            int gr = row0 + r;
            float4 v = make_float4(0.f, 0.f, 0.f, 0.f);
            if (gr < n) v = *(const float4*)&g_h[gr * EMB + k0 + q * 4];
            *(float4*)&sA[r * 68 + q * 4] = v;
        }
        __syncthreads();
        #pragma unroll
        for (int kk = 0; kk < 64; kk++) {
            float4 w = *(const float4*)&sM[(k0 + kk) * 32 + cid * 4];
            float a0 = sA[rid * 68 + kk];
            float a1 = sA[(rid + 32) * 68 + kk];
            acc0[0] += a0 * w.x; acc0[1] += a0 * w.y;
            acc0[2] += a0 * w.z; acc0[3] += a0 * w.w;
            acc1[0] += a1 * w.x; acc1[1] += a1 * w.y;
            acc1[2] += a1 * w.z; acc1[3] += a1 * w.w;
        }
    }
    int r0 = row0 + rid, r1 = row0 + rid + 32;
    bool v0 = r0 < n, v1 = r1 < n;
    if (v0) *(float4*)&scores[r0 * 32 + cid * 4] =
        make_float4(acc0[0], acc0[1], acc0[2], acc0[3]);
    if (v1) *(float4*)&scores[r1 * 32 + cid * 4] =
        make_float4(acc1[0], acc1[1], acc1[2], acc1[3]);

    // ---- fused per-block column max -> atomicMax ----
    const float NEG = -3.402823466e38f;
    float mx[4];
    #pragma unroll
    for (int c = 0; c < 4; c++) {
        float m0 = v0 ? acc0[c] : NEG;
        float m1 = v1 ? acc1[c] : NEG;
        mx[c] = fmaxf(m0, m1);
    }
    // reduce over the 4 rows sharing each (warp,cid): lanes cid, cid+8, +16, +24
    #pragma unroll
    for (int off = 8; off < 32; off <<= 1) {
        #pragma unroll
        for (int c = 0; c < 4; c++) {
            float o = __shfl_down_sync(0xFFFFFFFFu, mx[c], off);
            mx[c] = fmaxf(mx[c], o);
        }
    }
    int lane = tid & 31, wrp = tid >> 5;
    if (lane < 8) {
        #pragma unroll
        for (int c = 0; c < 4; c++) sMax[wrp][lane * 4 + c] = mx[c];
    }
    __syncthreads();
    if (wrp == 0) {                           // lane = column b (0..31)
        float m = sMax[0][lane];
        #pragma unroll
        for (int i = 1; i < 8; i++) m = fmaxf(m, sMax[i][lane]);
        atomicMax(&g_colmax[lane], fenc(m));
    }
}

// ---------------- 9. column logsumexp / write -------------------------------
__global__ void colsum_kernel(const float* __restrict__ s, int n) {
    __shared__ float sm[8][32];
    int lane = threadIdx.x & 31, wid = threadIdx.x >> 5;
    float mx = fdec(g_colmax[lane]);
    float acc = 0.0f;
    for (int row = blockIdx.x * 8 + wid; row < n; row += gridDim.x * 8)
        acc += expf(s[row * 32 + lane] - mx);
    sm[wid][lane] = acc;
    __syncthreads();
    if (wid == 0) {
        #pragma unroll
        for (int i = 1; i < 8; i++) acc += sm[i][lane];
        atomicAdd(&g_colsum[lane], acc);
    }
}

__global__ void logsm_kernel(float* __restrict__ s, int n) {
    __shared__ float smax[32], slog[32];
    if (threadIdx.x < 32) {
        smax[threadIdx.x] = fdec(g_colmax[threadIdx.x]);
        slog[threadIdx.x] = logf(g_colsum[threadIdx.x]);
    }
    __syncthreads();
    int tot = n * 32;
    for (int i = blockIdx.x * blockDim.x + threadIdx.x; i < tot;
         i += gridDim.x * blockDim.x) {
        int b = i & 31;
        s[i] = s[i] - smax[b] - slog[b];
    }
}

// ---------------- launch -----------------------------------------------------
extern "C" void kernel_launch(void* const* d_in, const int* in_sizes, int n_in,
                              void* d_out, int out_size) {
    const float* x    = (const float*)d_in[0];
    const void*  ei   = d_in[1];
    const float* lh   = (const float*)d_in[2];
    const float* W1r  = (const float*)d_in[3];
    const float* W1o  = (const float*)d_in[4];
    const float* b1   = (const float*)d_in[5];
    const float* W2r  = (const float*)d_in[6];
    const float* W2o  = (const float*)d_in[7];
    const float* b2   = (const float*)d_in[8];
    const float* Wp   = (const float*)d_in[9];
    const float* bp   = (const float*)d_in[10];
    float* out = (float*)d_out;

    int n = in_sizes[0] / FEAT;      // 50000
    int e = in_sizes[1] / 2;         // 640000

    detect_kernel<<<1, 32>>>(ei, n);
    init_kernel<<<(n + 255) / 256, 256>>>(n);
    hist_kernel<<<(e + 255) / 256, 256>>>(ei, e);
    scan_kernel<<<1, 1024>>>(n);
    fill_kernel<<<(e + 255) / 256, 256>>>(ei, e);

    dim3 ggrid((n + 63) / 64, 2);
    // layer 1
    rgcn_gemm_kernel<<<ggrid, 256>>>(x, W1r, W1o, b1, n);
    agg_kernel<<<(n * 32 + 255) / 256, 256>>>(n);
    // layer 2 (A = nullptr -> read g_h)
    rgcn_gemm_kernel<<<ggrid, 256>>>(nullptr, W2r, W2o, b2, n);
    agg_kernel<<<(n * 32 + 255) / 256, 256>>>(n);

    proj_kernel<<<BDIM, 128>>>(lh, Wp, bp);
    scores_kernel<<<(n + 63) / 64, 256>>>(out, n);   // fused colmax
    colsum_kernel<<<592, 256>>>(out, n);
    logsm_kernel<<<2048, 256>>>(out, n);
}

// round 4
// speedup vs baseline: 1.0880x; 1.0880x over previous
#include <cuda_runtime.h>
#include <cuda_bf16.h>
#include <math.h>

// Problem constants (fixed by the reference)
#define N_MAX   50000
#define E_MAX   640000
#define FEAT    128
#define EMB     128
#define HID     512
#define BDIM    32
#define SCAN_B  256
#define NBLK_MAX ((N_MAX + SCAN_B - 1) / SCAN_B)

// ---------------- scratch (static device globals: allocation-guard safe) ---
__device__ int   g_deg [N_MAX];
__device__ int   g_ptr [N_MAX + 1];
__device__ int   g_fill[N_MAX];
__device__ int   g_srcs[E_MAX];
__device__ int   g_bsum[NBLK_MAX];
__device__ int   g_boff[NBLK_MAX];
__device__ float g_t   [N_MAX * EMB];   // h @ W_rel
__device__ float g_root[N_MAX * EMB];   // h @ W_root + b
__device__ float g_h   [N_MAX * EMB];   // layer output
__device__ float g_m   [BDIM * EMB];    // message embed
__device__ unsigned g_colmax[BDIM];     // encoded-float max per column
__device__ float    g_colsum[BDIM];
__device__ int   g_is64;

// ---------------- helpers --------------------------------------------------
__device__ __forceinline__ unsigned fenc(float f) {
    unsigned u = __float_as_uint(f);
    return (u & 0x80000000u) ? ~u : (u | 0x80000000u);
}
__device__ __forceinline__ float fdec(unsigned u) {
    return (u & 0x80000000u) ? __uint_as_float(u & 0x7FFFFFFFu)
                             : __uint_as_float(~u);
}
__device__ __forceinline__ int edge_at(const void* ei, long long idx) {
    if (g_is64) return (int)((const long long*)ei)[idx];
    return ((const int*)ei)[idx];
}

// ---------------- 0. dtype detect (int64 vs silently-downcast int32) -------
__global__ void detect_kernel(const void* ei, int n) {
    if (blockIdx.x == 0 && threadIdx.x == 0) {
        const long long* p = (const long long*)ei;
        int ok = 1;
        for (int i = 0; i < 256; i++) {
            long long v = p[i];
            if (v < 0 || v >= (long long)n) { ok = 0; break; }
        }
        g_is64 = ok;
    }
}

// ---------------- 1. init --------------------------------------------------
__global__ void init_kernel(int n) {
    int i = blockIdx.x * blockDim.x + threadIdx.x;
    if (i < n) { g_deg[i] = 0; g_fill[i] = 0; }
    if (i < BDIM) { g_colmax[i] = 0u; g_colsum[i] = 0.0f; }
}

// ---------------- 2. degree histogram --------------------------------------
__global__ void hist_kernel(const void* ei, int e) {
    int i = blockIdx.x * blockDim.x + threadIdx.x;
    if (i < e) {
        int d = edge_at(ei, (long long)e + i);
        atomicAdd(&g_deg[d], 1);
    }
}

// ---------------- 3. scan: 3-phase (reduce / scan-sums / scan-tiles) -------
// Phase A: per-block sum of a 256-wide tile of g_deg.
__global__ void scanA_kernel(int n) {
    __shared__ int ws[8];
    int tid = threadIdx.x, lane = tid & 31, wrp = tid >> 5;
    int i = blockIdx.x * SCAN_B + tid;
    int v = (i < n) ? g_deg[i] : 0;
    #pragma unroll
    for (int off = 16; off > 0; off >>= 1)
        v += __shfl_down_sync(0xFFFFFFFFu, v, off);
    if (lane == 0) ws[wrp] = v;
    __syncthreads();
    if (tid == 0) {
        int s = 0;
        #pragma unroll
        for (int w = 0; w < 8; w++) s += ws[w];
        g_bsum[blockIdx.x] = s;
    }
}

// Phase B: single small block exclusive-scans nblk block sums.
__global__ void scanB_kernel(int nblk, int n) {
    __shared__ int warp_sums[32];
    int tid = threadIdx.x, lane = tid & 31, wrp = tid >> 5;
    int v = (tid < nblk) ? g_bsum[tid] : 0;
    int s = v;
    #pragma unroll
    for (int off = 1; off < 32; off <<= 1) {
        int t = __shfl_up_sync(0xFFFFFFFFu, s, off);
        if (lane >= off) s += t;
    }
    if (lane == 31) warp_sums[wrp] = s;
    __syncthreads();
    if (wrp == 0) {
        int ws = (lane < 8) ? warp_sums[lane] : 0;
        int ss = ws;
        #pragma unroll
        for (int off = 1; off < 8; off <<= 1) {
            int t = __shfl_up_sync(0xFFFFFFFFu, ss, off);
            if (lane >= off) ss += t;
        }
        if (lane < 8) warp_sums[lane] = ss - ws;      // exclusive warp offsets
        if (lane == 7) warp_sums[31] = ss;            // total
    }
    __syncthreads();
    if (tid < nblk) g_boff[tid] = warp_sums[wrp] + s - v;   // exclusive
    if (tid == 0) g_ptr[n] = warp_sums[31];
}

// Phase C: per-block local scan + block offset -> exclusive g_ptr.
__global__ void scanC_kernel(int n) {
    __shared__ int warp_off[8];
    int tid = threadIdx.x, lane = tid & 31, wrp = tid >> 5;
    int i = blockIdx.x * SCAN_B + tid;
    int v = (i < n) ? g_deg[i] : 0;
    int s = v;
    #pragma unroll
    for (int off = 1; off < 32; off <<= 1) {
        int t = __shfl_up_sync(0xFFFFFFFFu, s, off);
        if (lane >= off) s += t;
    }
    if (lane == 31) warp_off[wrp] = s;
    __syncthreads();
    if (wrp == 0 && lane < 8) {
        int ws = warp_off[lane];
        int ss = ws;
        #pragma unroll
        for (int off = 1; off < 8; off <<= 1) {
            int t = __shfl_up_sync(0xFFu, ss, off);
            if (lane >= off) ss += t;
        }
        warp_off[lane] = ss - ws;                     // exclusive warp offsets
    }
    __syncthreads();
    if (i < n) g_ptr[i] = g_boff[blockIdx.x] + warp_off[wrp] + s - v;
}

// ---------------- 4. CSR fill ------------------------------------------------
__global__ void fill_kernel(const void* ei, int e) {
    int i = blockIdx.x * blockDim.x + threadIdx.x;
    if (i < e) {
        int d = edge_at(ei, (long long)e + i);
        int s = edge_at(ei, (long long)i);
        int pos = g_ptr[d] + atomicAdd(&g_fill[d], 1);
        g_srcs[pos] = s;
    }
}

// ---------------- 5. layer GEMM: t = A@W_rel ; root = A@W_root + b ----------
// Block 256 threads, 64-row tile. Thread: 8 rows x 4 cols, rows paired into
// fma.rn.f32x2 (FFMA2) accumulators. A==nullptr means read from g_h.
__global__ __launch_bounds__(256) void rgcn_gemm_kernel(
        const float* __restrict__ A,
        const float* __restrict__ Wrel,
        const float* __restrict__ Wroot,
        const float* __restrict__ bias,
        int n)
{
    const float* Ap = A ? A : g_h;
    const float* W  = (blockIdx.y == 0) ? Wrel : Wroot;
    float*       O  = (blockIdx.y == 0) ? g_t  : g_root;

    __shared__ float sAT[32 * 64];     // [k][row]  (transposed A tile)
    __shared__ float sB [32 * 128];    // [k][col]

    int tid  = threadIdx.x;
    int cid  = tid & 31;               // column quad (cols cid*4..+3)
    int wid  = tid >> 5;               // row group  (rows wid*8..+7)
    int row0 = blockIdx.x * 64;

    unsigned long long acc[4][4];      // [rowpair][col] ; pair = rows (2p,2p+1)
    #pragma unroll
    for (int p = 0; p < 4; p++)
        #pragma unroll
        for (int c = 0; c < 4; c++) acc[p][c] = 0ULL;

    for (int k0 = 0; k0 < FEAT; k0 += 32) {
        #pragma unroll
        for (int i = 0; i < 2; i++) {
            int li = tid + i * 256;            // 0..511
            int r = li >> 3, q = li & 7;       // r 0..63, q 0..7
            int gr = row0 + r;
            float4 v = make_float4(0.f, 0.f, 0.f, 0.f);
            if (gr < n) v = *(const float4*)&Ap[gr * FEAT + k0 + q * 4];
            sAT[(q * 4 + 0) * 64 + r] = v.x;
            sAT[(q * 4 + 1) * 64 + r] = v.y;
            sAT[(q * 4 + 2) * 64 + r] = v.z;
            sAT[(q * 4 + 3) * 64 + r] = v.w;
        }
        #pragma unroll
        for (int i = 0; i < 4; i++) {
            int li = tid + i * 256;            // 0..1023
            int r = li >> 5, q = li & 31;
            *(float4*)&sB[r * 128 + q * 4] =
                *(const float4*)&W[(k0 + r) * EMB + q * 4];
        }
        __syncthreads();

        #pragma unroll
        for (int kk = 0; kk < 32; kk++) {
            unsigned long long ap[4];
            #pragma unroll
            for (int p = 0; p < 4; p++)
                ap[p] = *(const unsigned long long*)
                            &sAT[kk * 64 + wid * 8 + p * 2];
            float4 bv = *(const float4*)&sB[kk * 128 + cid * 4];
            unsigned long long bd[4];
            unsigned bu;
            bu = __float_as_uint(bv.x);
            asm("mov.b64 %0, {%1, %1};" : "=l"(bd[0]) : "r"(bu));
            bu = __float_as_uint(bv.y);
            asm("mov.b64 %0, {%1, %1};" : "=l"(bd[1]) : "r"(bu));
            bu = __float_as_uint(bv.z);
            asm("mov.b64 %0, {%1, %1};" : "=l"(bd[2]) : "r"(bu));
            bu = __float_as_uint(bv.w);
            asm("mov.b64 %0, {%1, %1};" : "=l"(bd[3]) : "r"(bu));
            #pragma unroll
            for (int p = 0; p < 4; p++)
                #pragma unroll
                for (int c = 0; c < 4; c++)
                    asm("fma.rn.f32x2 %0, %1, %2, %0;"
                        : "+l"(acc[p][c]) : "l"(ap[p]), "l"(bd[c]));
        }
        __syncthreads();
    }

    float4 bb = make_float4(0.f, 0.f, 0.f, 0.f);
    if (blockIdx.y == 1) bb = *(const float4*)&bias[cid * 4];

    #pragma unroll
    for (int p = 0; p < 4; p++) {
        float lo[4], hi[4];
        #pragma unroll
        for (int c = 0; c < 4; c++) {
            unsigned ulo, uhi;
            asm("mov.b64 {%0, %1}, %2;" : "=r"(ulo), "=r"(uhi) : "l"(acc[p][c]));
            lo[c] = __uint_as_float(ulo);
            hi[c] = __uint_as_float(uhi);
        }
        int r0 = row0 + wid * 8 + p * 2;
        if (r0 < n)
            *(float4*)&O[r0 * EMB + cid * 4] =
                make_float4(lo[0] + bb.x, lo[1] + bb.y, lo[2] + bb.z, lo[3] + bb.w);
        if (r0 + 1 < n)
            *(float4*)&O[(r0 + 1) * EMB + cid * 4] =
                make_float4(hi[0] + bb.x, hi[1] + bb.y, hi[2] + bb.z, hi[3] + bb.w);
    }
}

// ---------------- 6. aggregate (warp per node, CSR gather, unroll 4) --------
__global__ __launch_bounds__(256) void agg_kernel(int n) {
    int idx  = blockIdx.x * blockDim.x + threadIdx.x;
    int g    = idx >> 5;
    int lane = idx & 31;
    if (g >= n) return;
    int beg = __ldg(&g_ptr[g]), end = __ldg(&g_ptr[g + 1]);
    const float4* t4 = (const float4*)g_t;
    float4 a0 = make_float4(0.f, 0.f, 0.f, 0.f);
    float4 a1 = make_float4(0.f, 0.f, 0.f, 0.f);
    float4 a2 = make_float4(0.f, 0.f, 0.f, 0.f);
    float4 a3 = make_float4(0.f, 0.f, 0.f, 0.f);
    int e = beg;
    for (; e + 4 <= end; e += 4) {
        int s0 = __ldg(&g_srcs[e]);
        int s1 = __ldg(&g_srcs[e + 1]);
        int s2 = __ldg(&g_srcs[e + 2]);
        int s3 = __ldg(&g_srcs[e + 3]);
        float4 v0 = t4[s0 * 32 + lane];
        float4 v1 = t4[s1 * 32 + lane];
        float4 v2 = t4[s2 * 32 + lane];
        float4 v3 = t4[s3 * 32 + lane];
        a0.x += v0.x; a0.y += v0.y; a0.z += v0.z; a0.w += v0.w;
        a1.x += v1.x; a1.y += v1.y; a1.z += v1.z; a1.w += v1.w;
        a2.x += v2.x; a2.y += v2.y; a2.z += v2.z; a2.w += v2.w;
        a3.x += v3.x; a3.y += v3.y; a3.z += v3.z; a3.w += v3.w;
    }
    for (; e < end; e++) {
        int s = __ldg(&g_srcs[e]);
        float4 v = t4[s * 32 + lane];
        a0.x += v.x; a0.y += v.y; a0.z += v.z; a0.w += v.w;
    }
    a0.x += a2.x; a0.y += a2.y; a0.z += a2.z; a0.w += a2.w;
    a1.x += a3.x; a1.y += a3.y; a1.z += a3.z; a1.w += a3.w;
    float inv = 1.0f / fmaxf((float)(end - beg), 1.0f);
    float4 r = ((const float4*)g_root)[g * 32 + lane];
    float4 h;
    h.x = fmaxf((a0.x + a1.x) * inv + r.x, 0.0f);
    h.y = fmaxf((a0.y + a1.y) * inv + r.y, 0.0f);
    h.z = fmaxf((a0.z + a1.z) * inv + r.z, 0.0f);
    h.w = fmaxf((a0.w + a1.w) * inv + r.w, 0.0f);
    ((float4*)g_h)[g * 32 + lane] = h;
}

// ---------------- 7. projection m = lh @ Wp + bp  [32,128] ------------------
__global__ void proj_kernel(const float* __restrict__ lh,
                            const float* __restrict__ Wp,
                            const float* __restrict__ bp) {
    __shared__ float sl[HID];
    int b = blockIdx.x;                     // 0..31
    int c = threadIdx.x;                    // 0..127
    for (int k = c; k < HID; k += 128) sl[k] = lh[b * HID + k];
    __syncthreads();
    float acc = bp[c];
    #pragma unroll 8
    for (int k = 0; k < HID; k++) acc += sl[k] * Wp[k * EMB + c];
    g_m[b * EMB + c] = acc;
}

// ---------------- 8. scores = h2 @ m^T  [n,32]  + fused column max ----------
__global__ __launch_bounds__(256) void scores_kernel(float* __restrict__ scores,
                                                     int n) {
    __shared__ float sM[128 * 32];          // transposed m: sM[k*32 + b]
    __shared__ float sA[64 * 68];           // 64 rows x 64-k chunk, pad 4
    __shared__ float sMax[8][32];           // per-warp column maxima
    int tid = threadIdx.x;
    for (int i = tid; i < BDIM * EMB; i += 256) {
        int b = i >> 7, k = i & 127;
        sM[k * 32 + b] = g_m[i];
    }
    int row0 = blockIdx.x * 64;
    int cid = tid & 7;                      // col quad (b = cid*4..+3)
    int rid = tid >> 3;                     // 0..31 ; rows rid, rid+32
    float acc0[4] = {0.f, 0.f, 0.f, 0.f};
    float acc1[4] = {0.f, 0.f, 0.f, 0.f};
    for (int k0 = 0; k0 < 128; k0 += 64) {
        __syncthreads();
        for (int i = tid; i < 64 * 16; i += 256) {     // 16 float4 per row
            int r = i >> 4, q = i & 15;
            int gr = row0 + r;
            float4 v = make_float4(0.f, 0.f, 0.f, 0.f);
            if (gr < n) v = *(const float4*)&g_h[gr * EMB + k0 + q * 4];
            *(float4*)&sA[r * 68 + q * 4] = v;
        }
        __syncthreads();
        #pragma unroll
        for (int kk = 0; kk < 64; kk++) {
            float4 w = *(const float4*)&sM[(k0 + kk) * 32 + cid * 4];
            float a0 = sA[rid * 68 + kk];
            float a1 = sA[(rid + 32) * 68 + kk];
            acc0[0] += a0 * w.x; acc0[1] += a0 * w.y;
            acc0[2] += a0 * w.z; acc0[3] += a0 * w.w;
            acc1[0] += a1 * w.x; acc1[1] += a1 * w.y;
            acc1[2] += a1 * w.z; acc1[3] += a1 * w.w;
        }
    }
    int r0 = row0 + rid, r1 = row0 + rid + 32;
    bool v0 = r0 < n, v1 = r1 < n;
    if (v0) *(float4*)&scores[r0 * 32 + cid * 4] =
        make_float4(acc0[0], acc0[1], acc0[2], acc0[3]);
    if (v1) *(float4*)&scores[r1 * 32 + cid * 4] =
        make_float4(acc1[0], acc1[1], acc1[2], acc1[3]);

    // ---- fused per-block column max -> atomicMax ----
    const float NEG = -3.402823466e38f;
    float mx[4];
    #pragma unroll
    for (int c = 0; c < 4; c++) {
        float m0 = v0 ? acc0[c] : NEG;
        float m1 = v1 ? acc1[c] : NEG;
        mx[c] = fmaxf(m0, m1);
    }
    #pragma unroll
    for (int off = 8; off < 32; off <<= 1) {
        #pragma unroll
        for (int c = 0; c < 4; c++) {
            float o = __shfl_down_sync(0xFFFFFFFFu, mx[c], off);
            mx[c] = fmaxf(mx[c], o);
        }
    }
    int lane = tid & 31, wrp = tid >> 5;
    if (lane < 8) {
        #pragma unroll
        for (int c = 0; c < 4; c++) sMax[wrp][lane * 4 + c] = mx[c];
    }
    __syncthreads();
    if (wrp == 0) {                           // lane = column b (0..31)
        float m = sMax[0][lane];
        #pragma unroll
        for (int i = 1; i < 8; i++) m = fmaxf(m, sMax[i][lane]);
        atomicMax(&g_colmax[lane], fenc(m));
    }
}

// ---------------- 9. column logsumexp / write -------------------------------
__global__ void colsum_kernel(const float* __restrict__ s, int n) {
    __shared__ float sm[8][32];
    int lane = threadIdx.x & 31, wid = threadIdx.x >> 5;
    float mx = fdec(g_colmax[lane]);
    float acc = 0.0f;
    for (int row = blockIdx.x * 8 + wid; row < n; row += gridDim.x * 8)
        acc += expf(s[row * 32 + lane] - mx);
    sm[wid][lane] = acc;
    __syncthreads();
    if (wid == 0) {
        #pragma unroll
        for (int i = 1; i < 8; i++) acc += sm[i][lane];
        atomicAdd(&g_colsum[lane], acc);
    }
}

__global__ void logsm_kernel(float* __restrict__ s, int n) {
    __shared__ float smax[32], slog[32];
    if (threadIdx.x < 32) {
        smax[threadIdx.x] = fdec(g_colmax[threadIdx.x]);
        slog[threadIdx.x] = logf(g_colsum[threadIdx.x]);
    }
    __syncthreads();
    int tot = n * 32;
    for (int i = blockIdx.x * blockDim.x + threadIdx.x; i < tot;
         i += gridDim.x * blockDim.x) {
        int b = i & 31;
        s[i] = s[i] - smax[b] - slog[b];
    }
}

// ---------------- launch -----------------------------------------------------
extern "C" void kernel_launch(void* const* d_in, const int* in_sizes, int n_in,
                              void* d_out, int out_size) {
    const float* x    = (const float*)d_in[0];
    const void*  ei   = d_in[1];
    const float* lh   = (const float*)d_in[2];
    const float* W1r  = (const float*)d_in[3];
    const float* W1o  = (const float*)d_in[4];
    const float* b1   = (const float*)d_in[5];
    const float* W2r  = (const float*)d_in[6];
    const float* W2o  = (const float*)d_in[7];
    const float* b2   = (const float*)d_in[8];
    const float* Wp   = (const float*)d_in[9];
    const float* bp   = (const float*)d_in[10];
    float* out = (float*)d_out;

    int n = in_sizes[0] / FEAT;      // 50000
    int e = in_sizes[1] / 2;         // 640000
    int nblk = (n + SCAN_B - 1) / SCAN_B;

    detect_kernel<<<1, 32>>>(ei, n);
    init_kernel<<<(n + 255) / 256, 256>>>(n);
    hist_kernel<<<(e + 255) / 256, 256>>>(ei, e);
    scanA_kernel<<<nblk, SCAN_B>>>(n);
    scanB_kernel<<<1, 256>>>(nblk, n);
    scanC_kernel<<<nblk, SCAN_B>>>(n);
    fill_kernel<<<(e + 255) / 256, 256>>>(ei, e);

    dim3 ggrid((n + 63) / 64, 2);
    // layer 1
    rgcn_gemm_kernel<<<ggrid, 256>>>(x, W1r, W1o, b1, n);
    agg_kernel<<<(n * 32 + 255) / 256, 256>>>(n);
    // layer 2 (A = nullptr -> read g_h)
    rgcn_gemm_kernel<<<ggrid, 256>>>(nullptr, W2r, W2o, b2, n);
    agg_kernel<<<(n * 32 + 255) / 256, 256>>>(n);

    proj_kernel<<<BDIM, 128>>>(lh, Wp, bp);
    scores_kernel<<<(n + 63) / 64, 256>>>(out, n);   // fused colmax
    colsum_kernel<<<592, 256>>>(out, n);
    logsm_kernel<<<2048, 256>>>(out, n);
}